// round 6
// baseline (speedup 1.0000x reference)
#include <cuda_runtime.h>
#include <cuda_bf16.h>

// ---------------- problem constants ----------------
#define Nn      12288
#define Ee      393216
#define Hh      256
#define WPR     384            // Nn/32 words per bitmap row
#define MAXNNZ  (2*Ee)
#define DOUT    128
#define NCLS    8
#define HCH     64             // D_OUT/2

// ---------------- device scratch (static, no allocation) ----------------
__device__ unsigned g_bmA[(size_t)Nn * WPR];   // A[i][j] bit
__device__ unsigned g_bmT[(size_t)Nn * WPR];   // A^T[i][j] bit
__device__ int      g_rowcnt[Nn];
__device__ int      g_rowptr[Nn + 1];
__device__ float    g_invrs[Nn];
__device__ int      g_col[MAXNNZ];
__device__ float    g_val[MAXNNZ];
__device__ float    g_x0[(size_t)Nn * Hh];
__device__ float    g_x1[(size_t)Nn * Hh];
__device__ float    g_s [(size_t)Nn * Hh];
__device__ float    g_hid[(size_t)Nn * HCH];
__device__ int      g_is64;

// ---------------- graph build ----------------
__global__ void clear_kernel() {
    int i = blockIdx.x * blockDim.x + threadIdx.x;
    int stride = gridDim.x * blockDim.x;
    const int total = Nn * WPR;
    for (int j = i; j < total; j += stride) { g_bmA[j] = 0u; g_bmT[j] = 0u; }
}

// int64-vs-int32 edge_index detection: if data is int64 (values < 12288),
// every odd 32-bit word (hi half) is zero. For int32 data the odd words are
// real indices and are essentially never all zero over 4096 samples.
__global__ void detect_kernel(const int* __restrict__ ei) {
    __shared__ int sh[256];
    int t = threadIdx.x;
    int v = 0;
    for (int i = t; i < 4096; i += 256) v |= ei[2 * i + 1];
    sh[t] = v; __syncthreads();
    for (int o = 128; o > 0; o >>= 1) { if (t < o) sh[t] |= sh[t + o]; __syncthreads(); }
    if (t == 0) g_is64 = (sh[0] == 0) ? 1 : 0;
}

__global__ void scatter_kernel(const void* __restrict__ ei_raw) {
    int e = blockIdx.x * blockDim.x + threadIdx.x;
    if (e >= Ee) return;
    int s, d;
    if (g_is64) {
        const long long* ei = (const long long*)ei_raw;
        s = (int)ei[e]; d = (int)ei[Ee + e];
    } else {
        const int* ei = (const int*)ei_raw;
        s = ei[e]; d = ei[Ee + e];
    }
    atomicOr(&g_bmA[(size_t)s * WPR + (d >> 5)], 1u << (d & 31));
    atomicOr(&g_bmT[(size_t)d * WPR + (s >> 5)], 1u << (s & 31));
}

__global__ void count_kernel() {
    int warp = (blockIdx.x * blockDim.x + threadIdx.x) >> 5;
    int lane = threadIdx.x & 31;
    if (warp >= Nn) return;
    int cu = 0, rs = 0;
    const size_t base = (size_t)warp * WPR;
    for (int w = lane; w < WPR; w += 32) {
        unsigned a = g_bmA[base + w];
        unsigned t = g_bmT[base + w];
        cu += __popc(a | t);
        rs += __popc(a) + __popc(t);
    }
#pragma unroll
    for (int off = 16; off > 0; off >>= 1) {
        cu += __shfl_down_sync(0xFFFFFFFFu, cu, off);
        rs += __shfl_down_sync(0xFFFFFFFFu, rs, off);
    }
    if (lane == 0) {
        g_rowcnt[warp] = cu;
        g_invrs[warp] = 1.0f / ((float)rs + 1e-8f);
    }
}

__global__ void scan_kernel() {   // exclusive scan of 12288 counts, 1 block x 1024
    __shared__ int sh[1024];
    int t = threadIdx.x;
    int base = t * 12;
    int loc[12]; int s = 0;
#pragma unroll
    for (int i = 0; i < 12; i++) { loc[i] = g_rowcnt[base + i]; s += loc[i]; }
    sh[t] = s; __syncthreads();
    for (int off = 1; off < 1024; off <<= 1) {
        int v = (t >= off) ? sh[t - off] : 0;
        __syncthreads();
        sh[t] += v;
        __syncthreads();
    }
    int run = (t == 0) ? 0 : sh[t - 1];
#pragma unroll
    for (int i = 0; i < 12; i++) { g_rowptr[base + i] = run; run += loc[i]; }
    if (t == 1023) g_rowptr[Nn] = run;
}

__global__ void fill_kernel() {
    int row  = (blockIdx.x * blockDim.x + threadIdx.x) >> 5;
    int lane = threadIdx.x & 31;
    if (row >= Nn) return;
    const size_t bb = (size_t)row * WPR;
    int base = g_rowptr[row];
    float inv = g_invrs[row];
    for (int w0 = 0; w0 < WPR; w0 += 32) {
        int w = w0 + lane;
        unsigned a = g_bmA[bb + w];
        unsigned t = g_bmT[bb + w];
        unsigned u = a | t;
        int c = __popc(u);
        int x = c;
#pragma unroll
        for (int off = 1; off < 32; off <<= 1) {
            int y = __shfl_up_sync(0xFFFFFFFFu, x, off);
            if (lane >= off) x += y;
        }
        int tot = __shfl_sync(0xFFFFFFFFu, x, 31);
        int pos = base + x - c;
        while (u) {
            int b = __ffs(u) - 1;
            float v = (float)(((a >> b) & 1u) + ((t >> b) & 1u)) * inv;
            g_col[pos] = w * 32 + b;
            g_val[pos] = v;
            ++pos;
            u &= u - 1;
        }
        base += tot;
    }
}

// ---------------- SpMM: s = x + adj_norm @ x   (x: [Nn, 256]) ----------------
__global__ void __launch_bounds__(256) spmm_kernel(const float* __restrict__ x,
                                                   float* __restrict__ s) {
    int row = blockIdx.x;
    int f = threadIdx.x;
    __shared__ int   scol[256];
    __shared__ float sval[256];
    float acc = x[(size_t)row * Hh + f];
    int start = g_rowptr[row], end = g_rowptr[row + 1];
    for (int c = start; c < end; c += 256) {
        int m = end - c; if (m > 256) m = 256;
        if (f < m) { scol[f] = g_col[c + f]; sval[f] = g_val[c + f]; }
        __syncthreads();
        for (int j = 0; j < m; ++j)
            acc = fmaf(sval[j], x[(size_t)scol[j] * Hh + f], acc);
        __syncthreads();
    }
    s[(size_t)row * Hh + f] = acc;
}

// ---------------- generic SGEMM:  C = act(A @ W^T + bias) ----------------
// A: [M,K] row-major, W: [Nout,K] row-major, C: [M,Nout].
// BM=128, BN=128, BK=8, 256 threads, 8x8 per thread, register prefetch.
template <int RELU>
__global__ void __launch_bounds__(256, 2)
gemm_kernel(const float* __restrict__ A, const float* __restrict__ W,
            const float* __restrict__ bias, float* __restrict__ C,
            int M, int Nout, int K) {
    __shared__ float As[8][128];
    __shared__ float Ws[8][128];
    int tid = threadIdx.x;
    int bx = blockIdx.x, by = blockIdx.y;

    int loadRow = tid >> 1;            // 0..127
    int loadK4  = (tid & 1) * 4;       // 0 or 4
    int ty = tid >> 4, tx = tid & 15;  // 16x16 thread grid

    float acc[8][8];
#pragma unroll
    for (int i = 0; i < 8; i++)
#pragma unroll
        for (int j = 0; j < 8; j++) acc[i][j] = 0.0f;

    size_t aBase = (size_t)(by * 128 + loadRow) * K + loadK4;
    int wRow = bx * 128 + loadRow;
    bool wValid = wRow < Nout;
    size_t wBase = (size_t)(wValid ? wRow : 0) * K + loadK4;

    const float4 z4 = make_float4(0.f, 0.f, 0.f, 0.f);
    int kIter = K >> 3;
    float4 av = *(const float4*)(A + aBase);
    float4 wv = wValid ? *(const float4*)(W + wBase) : z4;

    for (int it = 0; it < kIter; ++it) {
        As[loadK4 + 0][loadRow] = av.x;
        As[loadK4 + 1][loadRow] = av.y;
        As[loadK4 + 2][loadRow] = av.z;
        As[loadK4 + 3][loadRow] = av.w;
        Ws[loadK4 + 0][loadRow] = wv.x;
        Ws[loadK4 + 1][loadRow] = wv.y;
        Ws[loadK4 + 2][loadRow] = wv.z;
        Ws[loadK4 + 3][loadRow] = wv.w;
        __syncthreads();
        if (it + 1 < kIter) {
            int off = (it + 1) * 8;
            av = *(const float4*)(A + aBase + off);
            wv = wValid ? *(const float4*)(W + wBase + off) : z4;
        }
#pragma unroll
        for (int k = 0; k < 8; ++k) {
            float4 a0 = *(const float4*)(&As[k][ty * 8]);
            float4 a1 = *(const float4*)(&As[k][ty * 8 + 4]);
            float4 b0 = *(const float4*)(&Ws[k][tx * 8]);
            float4 b1 = *(const float4*)(&Ws[k][tx * 8 + 4]);
            float aR[8] = {a0.x, a0.y, a0.z, a0.w, a1.x, a1.y, a1.z, a1.w};
            float bR[8] = {b0.x, b0.y, b0.z, b0.w, b1.x, b1.y, b1.z, b1.w};
#pragma unroll
            for (int i = 0; i < 8; i++)
#pragma unroll
                for (int j = 0; j < 8; j++)
                    acc[i][j] = fmaf(aR[i], bR[j], acc[i][j]);
        }
        __syncthreads();
    }

    int cRow0 = by * 128 + ty * 8;
    int cCol0 = bx * 128 + tx * 8;
#pragma unroll
    for (int i = 0; i < 8; i++) {
#pragma unroll
        for (int j = 0; j < 8; j++) {
            int col = cCol0 + j;
            if (col < Nout) {
                float v = acc[i][j] + bias[col];
                if (RELU) v = fmaxf(v, 0.0f);
                C[(size_t)(cRow0 + i) * Nout + col] = v;
            }
        }
    }
}

// ---------------- classifier tail:  hl = hid @ hc_w2^T + b2 ----------------
__global__ void __launch_bounds__(256) hc2_kernel(const float* __restrict__ hid,
                                                  const float* __restrict__ w2,
                                                  const float* __restrict__ b2,
                                                  float* __restrict__ out) {
    __shared__ float sw[NCLS * HCH];
    int t = threadIdx.x;
    for (int i = t; i < NCLS * HCH; i += 256) sw[i] = w2[i];
    __syncthreads();
    int g = blockIdx.x * 256 + t;
    int n = g >> 3, c = g & 7;
    float acc = b2[c];
    const float* hrow = hid + (size_t)n * HCH;
    const float* wrow = sw + c * HCH;
#pragma unroll 8
    for (int k = 0; k < HCH; ++k) acc = fmaf(hrow[k], wrow[k], acc);
    out[g] = acc;
}

// ---------------- column mean of node_embeddings ----------------
__global__ void __launch_bounds__(256) mean_kernel(const float* __restrict__ ne,
                                                   float* __restrict__ out) {
    int f = blockIdx.x;        // 0..127
    int t = threadIdx.x;
    float acc = 0.0f;
    for (int r = t; r < Nn; r += 256) acc += ne[(size_t)r * DOUT + f];
    __shared__ float sh[256];
    sh[t] = acc; __syncthreads();
    for (int o = 128; o > 0; o >>= 1) { if (t < o) sh[t] += sh[t + o]; __syncthreads(); }
    if (t == 0) out[f] = sh[0] * (1.0f / (float)Nn);
}

// ---------------- launch ----------------
extern "C" void kernel_launch(void* const* d_in, const int* in_sizes, int n_in,
                              void* d_out, int out_size) {
    const float* X     = (const float*)d_in[0];
    const void*  EI    = d_in[1];
    const float* enc_w1 = (const float*)d_in[2];
    const float* enc_b1 = (const float*)d_in[3];
    const float* enc_w2 = (const float*)d_in[4];
    const float* enc_b2 = (const float*)d_in[5];
    const float* gin_w  = (const float*)d_in[6];
    const float* gin_b  = (const float*)d_in[7];
    const float* gl_w   = (const float*)d_in[8];
    const float* gl_b   = (const float*)d_in[9];
    const float* gout_w = (const float*)d_in[10];
    const float* gout_b = (const float*)d_in[11];
    const float* proj_w = (const float*)d_in[12];
    const float* proj_b = (const float*)d_in[13];
    const float* hc_w1  = (const float*)d_in[14];
    const float* hc_b1  = (const float*)d_in[15];
    const float* hc_w2  = (const float*)d_in[16];
    const float* hc_b2  = (const float*)d_in[17];

    float *x0, *x1, *s, *hid;
    cudaGetSymbolAddress((void**)&x0, g_x0);
    cudaGetSymbolAddress((void**)&x1, g_x1);
    cudaGetSymbolAddress((void**)&s, g_s);
    cudaGetSymbolAddress((void**)&hid, g_hid);

    float* out = (float*)d_out;
    float* ne = out;                       // [Nn, 128]
    float* hl = out + (size_t)Nn * DOUT;   // [Nn, 8]
    float* gf = hl + (size_t)Nn * NCLS;    // [128]

    // graph build (deterministic, recomputed every call)
    clear_kernel<<<2048, 256>>>();
    detect_kernel<<<1, 256>>>((const int*)EI);
    scatter_kernel<<<Ee / 256, 256>>>(EI);
    count_kernel<<<Nn / 8, 256>>>();
    scan_kernel<<<1, 1024>>>();
    fill_kernel<<<Nn / 8, 256>>>();

    dim3 g256(2, Nn / 128);    // Nout=256
    dim3 g128(1, Nn / 128);    // Nout<=128

    // encoder
    gemm_kernel<1><<<g256, 256>>>(X,  enc_w1, enc_b1, x0, Nn, Hh, 256);
    gemm_kernel<0><<<g256, 256>>>(x0, enc_w2, enc_b2, x1, Nn, Hh, Hh);
    // GNN input proj
    gemm_kernel<1><<<g256, 256>>>(x1, gin_w, gin_b, x0, Nn, Hh, Hh);
    // 3 message-passing layers
    for (int i = 0; i < 3; i++) {
        spmm_kernel<<<Nn, 256>>>(x0, s);
        gemm_kernel<1><<<g256, 256>>>(s, gl_w + (size_t)i * Hh * Hh,
                                      gl_b + (size_t)i * Hh, x0, Nn, Hh, Hh);
    }
    // output proj
    gemm_kernel<0><<<g256, 256>>>(x0, gout_w, gout_b, x1, Nn, Hh, Hh);
    // node embeddings (written straight to d_out)
    gemm_kernel<1><<<g128, 256>>>(x1, proj_w, proj_b, ne, Nn, DOUT, Hh);
    // hierarchy classifier
    gemm_kernel<1><<<g128, 256>>>(ne, hc_w1, hc_b1, hid, Nn, HCH, DOUT);
    hc2_kernel<<<(Nn * NCLS) / 256, 256>>>(hid, hc_w2, hc_b2, hl);
    // global mean
    mean_kernel<<<DOUT, 256>>>(ne, gf);
}

// round 8
// speedup vs baseline: 2.6452x; 2.6452x over previous
#include <cuda_runtime.h>
#include <cuda_bf16.h>

// ---------------- problem constants ----------------
#define Nn      12288
#define Ee      393216
#define Hh      256
#define WPR     384            // Nn/32 words per bitmap row
#define MAXNNZ  (2*Ee)
#define DOUT    128
#define NCLS    8
#define HCH     64             // D_OUT/2

// ---------------- device scratch (static, no allocation) ----------------
__device__ unsigned g_bmA[(size_t)Nn * WPR];   // A[i][j] bit
__device__ unsigned g_bmT[(size_t)Nn * WPR];   // A^T[i][j] bit
__device__ int      g_rowcnt[Nn];
__device__ int      g_rowptr[Nn + 1];
__device__ float    g_invrs[Nn];
__device__ int      g_col[MAXNNZ];
__device__ float    g_val[MAXNNZ];
__device__ float    g_x0[(size_t)Nn * Hh];
__device__ float    g_x1[(size_t)Nn * Hh];
__device__ float    g_s [(size_t)Nn * Hh];
__device__ float    g_hid[(size_t)Nn * HCH];
__device__ int      g_is64;

// ---------------- graph build ----------------
__global__ void clear_kernel() {
    int i = blockIdx.x * blockDim.x + threadIdx.x;
    int stride = gridDim.x * blockDim.x;
    const int total = Nn * WPR;
    for (int j = i; j < total; j += stride) { g_bmA[j] = 0u; g_bmT[j] = 0u; }
}

// int64-vs-int32 edge_index detection: if data is int64 (values < 12288),
// every odd 32-bit word (hi half) is zero.
__global__ void detect_kernel(const int* __restrict__ ei) {
    __shared__ int sh[256];
    int t = threadIdx.x;
    int v = 0;
    for (int i = t; i < 4096; i += 256) v |= ei[2 * i + 1];
    sh[t] = v; __syncthreads();
    for (int o = 128; o > 0; o >>= 1) { if (t < o) sh[t] |= sh[t + o]; __syncthreads(); }
    if (t == 0) g_is64 = (sh[0] == 0) ? 1 : 0;
}

__global__ void scatter_kernel(const void* __restrict__ ei_raw) {
    int e = blockIdx.x * blockDim.x + threadIdx.x;
    if (e >= Ee) return;
    int s, d;
    if (g_is64) {
        const long long* ei = (const long long*)ei_raw;
        s = (int)ei[e]; d = (int)ei[Ee + e];
    } else {
        const int* ei = (const int*)ei_raw;
        s = ei[e]; d = ei[Ee + e];
    }
    atomicOr(&g_bmA[(size_t)s * WPR + (d >> 5)], 1u << (d & 31));
    atomicOr(&g_bmT[(size_t)d * WPR + (s >> 5)], 1u << (s & 31));
}

__global__ void count_kernel() {
    int warp = (blockIdx.x * blockDim.x + threadIdx.x) >> 5;
    int lane = threadIdx.x & 31;
    if (warp >= Nn) return;
    int cu = 0, rs = 0;
    const size_t base = (size_t)warp * WPR;
    for (int w = lane; w < WPR; w += 32) {
        unsigned a = g_bmA[base + w];
        unsigned t = g_bmT[base + w];
        cu += __popc(a | t);
        rs += __popc(a) + __popc(t);
    }
#pragma unroll
    for (int off = 16; off > 0; off >>= 1) {
        cu += __shfl_down_sync(0xFFFFFFFFu, cu, off);
        rs += __shfl_down_sync(0xFFFFFFFFu, rs, off);
    }
    if (lane == 0) {
        g_rowcnt[warp] = cu;
        g_invrs[warp] = 1.0f / ((float)rs + 1e-8f);
    }
}

__global__ void scan_kernel() {   // exclusive scan of 12288 counts, 1 block x 1024
    __shared__ int sh[1024];
    int t = threadIdx.x;
    int base = t * 12;
    int loc[12]; int s = 0;
#pragma unroll
    for (int i = 0; i < 12; i++) { loc[i] = g_rowcnt[base + i]; s += loc[i]; }
    sh[t] = s; __syncthreads();
    for (int off = 1; off < 1024; off <<= 1) {
        int v = (t >= off) ? sh[t - off] : 0;
        __syncthreads();
        sh[t] += v;
        __syncthreads();
    }
    int run = (t == 0) ? 0 : sh[t - 1];
#pragma unroll
    for (int i = 0; i < 12; i++) { g_rowptr[base + i] = run; run += loc[i]; }
    if (t == 1023) g_rowptr[Nn] = run;
}

__global__ void fill_kernel() {
    int row  = (blockIdx.x * blockDim.x + threadIdx.x) >> 5;
    int lane = threadIdx.x & 31;
    if (row >= Nn) return;
    const size_t bb = (size_t)row * WPR;
    int base = g_rowptr[row];
    float inv = g_invrs[row];
    for (int w0 = 0; w0 < WPR; w0 += 32) {
        int w = w0 + lane;
        unsigned a = g_bmA[bb + w];
        unsigned t = g_bmT[bb + w];
        unsigned u = a | t;
        int c = __popc(u);
        int x = c;
#pragma unroll
        for (int off = 1; off < 32; off <<= 1) {
            int y = __shfl_up_sync(0xFFFFFFFFu, x, off);
            if (lane >= off) x += y;
        }
        int tot = __shfl_sync(0xFFFFFFFFu, x, 31);
        int pos = base + x - c;
        while (u) {
            int b = __ffs(u) - 1;
            float v = (float)(((a >> b) & 1u) + ((t >> b) & 1u)) * inv;
            g_col[pos] = w * 32 + b;
            g_val[pos] = v;
            ++pos;
            u &= u - 1;
        }
        base += tot;
    }
}

// ---------------- SpMM: s = x + adj_norm @ x   (x: [Nn, 256]) ----------------
__global__ void __launch_bounds__(256) spmm_kernel(const float* __restrict__ x,
                                                   float* __restrict__ s) {
    int row = blockIdx.x;
    int f = threadIdx.x;
    __shared__ int   scol[256];
    __shared__ float sval[256];
    float acc = x[(size_t)row * Hh + f];
    int start = g_rowptr[row], end = g_rowptr[row + 1];
    for (int c = start; c < end; c += 256) {
        int m = end - c; if (m > 256) m = 256;
        if (f < m) { scol[f] = g_col[c + f]; sval[f] = g_val[c + f]; }
        __syncthreads();
        for (int j = 0; j < m; ++j)
            acc = fmaf(sval[j], x[(size_t)scol[j] * Hh + f], acc);
        __syncthreads();
    }
    s[(size_t)row * Hh + f] = acc;
}

// ---------------- tf32 tensor-core SGEMM:  C = act(A @ W^T + bias) ----------
// A: [M,K] rm, W: [Nout,K] rm, C: [M,Nout]. BM=BN=128, BK=16, 256 thr, 8 warps
// each computing a 32x64 warp tile via mma.sync.m16n8k8 tf32 (fp32 accum).
__device__ __forceinline__ unsigned f2tf32(float f) {
    unsigned r;
    asm("cvt.rna.tf32.f32 %0, %1;" : "=r"(r) : "f"(f));
    return r;
}

template <int RELU>
__global__ void __launch_bounds__(256, 2)
mma_gemm(const float* __restrict__ A, const float* __restrict__ W,
         const float* __restrict__ bias, float* __restrict__ C,
         int M, int Nout, int K) {
    __shared__ unsigned As[16][132];   // [k][m], pad 132 to spread banks
    __shared__ unsigned Ws[16][132];   // [k][n]

    const int tid  = threadIdx.x;
    const int wid  = tid >> 5;
    const int lane = tid & 31;
    const int g    = lane >> 2;        // 0..7
    const int tig  = lane & 3;         // 0..3
    const int wm   = wid & 3;          // 4 warps along M
    const int wn   = wid >> 2;         // 2 warps along N
    const int bx = blockIdx.x, by = blockIdx.y;

    // global-load assignment: thread covers rows r and r+64, 4 k-values each
    const int lr  = tid >> 2;          // 0..63
    const int kq  = (tid & 3) * 4;     // 0,4,8,12

    float acc[2][8][4];
#pragma unroll
    for (int mt = 0; mt < 2; mt++)
#pragma unroll
        for (int nt = 0; nt < 8; nt++)
#pragma unroll
            for (int i = 0; i < 4; i++) acc[mt][nt][i] = 0.0f;

    const size_t aRow0 = (size_t)(by * 128 + lr) * K;
    const size_t aRow1 = (size_t)(by * 128 + lr + 64) * K;
    const int wR0 = bx * 128 + lr, wR1 = bx * 128 + lr + 64;
    const bool v0 = wR0 < Nout, v1 = wR1 < Nout;
    const size_t wRow0 = (size_t)(v0 ? wR0 : 0) * K;
    const size_t wRow1 = (size_t)(v1 ? wR1 : 0) * K;
    const float4 z4 = make_float4(0.f, 0.f, 0.f, 0.f);

    const int kIter = K >> 4;
    float4 a0v = *(const float4*)(A + aRow0 + kq);
    float4 a1v = *(const float4*)(A + aRow1 + kq);
    float4 w0v = v0 ? *(const float4*)(W + wRow0 + kq) : z4;
    float4 w1v = v1 ? *(const float4*)(W + wRow1 + kq) : z4;

    for (int it = 0; it < kIter; ++it) {
        As[kq + 0][lr] = f2tf32(a0v.x);
        As[kq + 1][lr] = f2tf32(a0v.y);
        As[kq + 2][lr] = f2tf32(a0v.z);
        As[kq + 3][lr] = f2tf32(a0v.w);
        As[kq + 0][lr + 64] = f2tf32(a1v.x);
        As[kq + 1][lr + 64] = f2tf32(a1v.y);
        As[kq + 2][lr + 64] = f2tf32(a1v.z);
        As[kq + 3][lr + 64] = f2tf32(a1v.w);
        Ws[kq + 0][lr] = f2tf32(w0v.x);
        Ws[kq + 1][lr] = f2tf32(w0v.y);
        Ws[kq + 2][lr] = f2tf32(w0v.z);
        Ws[kq + 3][lr] = f2tf32(w0v.w);
        Ws[kq + 0][lr + 64] = f2tf32(w1v.x);
        Ws[kq + 1][lr + 64] = f2tf32(w1v.y);
        Ws[kq + 2][lr + 64] = f2tf32(w1v.z);
        Ws[kq + 3][lr + 64] = f2tf32(w1v.w);
        __syncthreads();

        if (it + 1 < kIter) {
            int off = (it + 1) * 16 + kq;
            a0v = *(const float4*)(A + aRow0 + off);
            a1v = *(const float4*)(A + aRow1 + off);
            w0v = v0 ? *(const float4*)(W + wRow0 + off) : z4;
            w1v = v1 ? *(const float4*)(W + wRow1 + off) : z4;
        }

#pragma unroll
        for (int ks = 0; ks < 2; ++ks) {
            const int k0 = ks * 8;
            unsigned af[2][4];
#pragma unroll
            for (int mt = 0; mt < 2; mt++) {
                int m = wm * 32 + mt * 16 + g;
                af[mt][0] = As[k0 + tig][m];
                af[mt][1] = As[k0 + tig][m + 8];
                af[mt][2] = As[k0 + tig + 4][m];
                af[mt][3] = As[k0 + tig + 4][m + 8];
            }
            unsigned bf[8][2];
#pragma unroll
            for (int nt = 0; nt < 8; nt++) {
                int n = wn * 64 + nt * 8 + g;
                bf[nt][0] = Ws[k0 + tig][n];
                bf[nt][1] = Ws[k0 + tig + 4][n];
            }
#pragma unroll
            for (int mt = 0; mt < 2; mt++)
#pragma unroll
                for (int nt = 0; nt < 8; nt++) {
                    asm volatile(
                        "mma.sync.aligned.m16n8k8.row.col.f32.tf32.tf32.f32 "
                        "{%0,%1,%2,%3}, {%4,%5,%6,%7}, {%8,%9}, {%0,%1,%2,%3};"
                        : "+f"(acc[mt][nt][0]), "+f"(acc[mt][nt][1]),
                          "+f"(acc[mt][nt][2]), "+f"(acc[mt][nt][3])
                        : "r"(af[mt][0]), "r"(af[mt][1]),
                          "r"(af[mt][2]), "r"(af[mt][3]),
                          "r"(bf[nt][0]), "r"(bf[nt][1]));
                }
        }
        __syncthreads();
    }

    // epilogue: bias + optional relu, float2 stores
    const int rBase = by * 128 + wm * 32;
    const int cBase = bx * 128 + wn * 64;
#pragma unroll
    for (int nt = 0; nt < 8; nt++) {
        int c0 = cBase + nt * 8 + 2 * tig;
        if (c0 < Nout) {
            float b0 = bias[c0], b1 = bias[c0 + 1];
#pragma unroll
            for (int mt = 0; mt < 2; mt++) {
                int r0 = rBase + mt * 16 + g;
                float x0 = acc[mt][nt][0] + b0;
                float x1 = acc[mt][nt][1] + b1;
                float x2 = acc[mt][nt][2] + b0;
                float x3 = acc[mt][nt][3] + b1;
                if (RELU) {
                    x0 = fmaxf(x0, 0.f); x1 = fmaxf(x1, 0.f);
                    x2 = fmaxf(x2, 0.f); x3 = fmaxf(x3, 0.f);
                }
                *(float2*)(C + (size_t)r0 * Nout + c0) = make_float2(x0, x1);
                *(float2*)(C + (size_t)(r0 + 8) * Nout + c0) = make_float2(x2, x3);
            }
        }
    }
}

// ---------------- classifier tail:  hl = hid @ hc_w2^T + b2 ----------------
__global__ void __launch_bounds__(256) hc2_kernel(const float* __restrict__ hid,
                                                  const float* __restrict__ w2,
                                                  const float* __restrict__ b2,
                                                  float* __restrict__ out) {
    __shared__ float sw[NCLS * HCH];
    int t = threadIdx.x;
    for (int i = t; i < NCLS * HCH; i += 256) sw[i] = w2[i];
    __syncthreads();
    int g = blockIdx.x * 256 + t;
    int n = g >> 3, c = g & 7;
    float acc = b2[c];
    const float* hrow = hid + (size_t)n * HCH;
    const float* wrow = sw + c * HCH;
#pragma unroll 8
    for (int k = 0; k < HCH; ++k) acc = fmaf(hrow[k], wrow[k], acc);
    out[g] = acc;
}

// ---------------- column mean of node_embeddings ----------------
__global__ void __launch_bounds__(256) mean_kernel(const float* __restrict__ ne,
                                                   float* __restrict__ out) {
    int f = blockIdx.x;        // 0..127
    int t = threadIdx.x;
    float acc = 0.0f;
    for (int r = t; r < Nn; r += 256) acc += ne[(size_t)r * DOUT + f];
    __shared__ float sh[256];
    sh[t] = acc; __syncthreads();
    for (int o = 128; o > 0; o >>= 1) { if (t < o) sh[t] += sh[t + o]; __syncthreads(); }
    if (t == 0) out[f] = sh[0] * (1.0f / (float)Nn);
}

// ---------------- launch ----------------
extern "C" void kernel_launch(void* const* d_in, const int* in_sizes, int n_in,
                              void* d_out, int out_size) {
    const float* X     = (const float*)d_in[0];
    const void*  EI    = d_in[1];
    const float* enc_w1 = (const float*)d_in[2];
    const float* enc_b1 = (const float*)d_in[3];
    const float* enc_w2 = (const float*)d_in[4];
    const float* enc_b2 = (const float*)d_in[5];
    const float* gin_w  = (const float*)d_in[6];
    const float* gin_b  = (const float*)d_in[7];
    const float* gl_w   = (const float*)d_in[8];
    const float* gl_b   = (const float*)d_in[9];
    const float* gout_w = (const float*)d_in[10];
    const float* gout_b = (const float*)d_in[11];
    const float* proj_w = (const float*)d_in[12];
    const float* proj_b = (const float*)d_in[13];
    const float* hc_w1  = (const float*)d_in[14];
    const float* hc_b1  = (const float*)d_in[15];
    const float* hc_w2  = (const float*)d_in[16];
    const float* hc_b2  = (const float*)d_in[17];

    float *x0, *x1, *s, *hid;
    cudaGetSymbolAddress((void**)&x0, g_x0);
    cudaGetSymbolAddress((void**)&x1, g_x1);
    cudaGetSymbolAddress((void**)&s, g_s);
    cudaGetSymbolAddress((void**)&hid, g_hid);

    float* out = (float*)d_out;
    float* ne = out;                       // [Nn, 128]
    float* hl = out + (size_t)Nn * DOUT;   // [Nn, 8]
    float* gf = hl + (size_t)Nn * NCLS;    // [128]

    // graph build (deterministic, recomputed every call)
    clear_kernel<<<2048, 256>>>();
    detect_kernel<<<1, 256>>>((const int*)EI);
    scatter_kernel<<<Ee / 256, 256>>>(EI);
    count_kernel<<<Nn / 8, 256>>>();
    scan_kernel<<<1, 1024>>>();
    fill_kernel<<<Nn / 8, 256>>>();

    dim3 g256(2, Nn / 128);    // Nout=256
    dim3 g128(1, Nn / 128);    // Nout<=128

    // encoder
    mma_gemm<1><<<g256, 256>>>(X,  enc_w1, enc_b1, x0, Nn, Hh, 256);
    mma_gemm<0><<<g256, 256>>>(x0, enc_w2, enc_b2, x1, Nn, Hh, Hh);
    // GNN input proj
    mma_gemm<1><<<g256, 256>>>(x1, gin_w, gin_b, x0, Nn, Hh, Hh);
    // 3 message-passing layers
    for (int i = 0; i < 3; i++) {
        spmm_kernel<<<Nn, 256>>>(x0, s);
        mma_gemm<1><<<g256, 256>>>(s, gl_w + (size_t)i * Hh * Hh,
                                   gl_b + (size_t)i * Hh, x0, Nn, Hh, Hh);
    }
    // output proj
    mma_gemm<0><<<g256, 256>>>(x0, gout_w, gout_b, x1, Nn, Hh, Hh);
    // node embeddings (written straight to d_out)
    mma_gemm<1><<<g128, 256>>>(x1, proj_w, proj_b, ne, Nn, DOUT, Hh);
    // hierarchy classifier
    mma_gemm<1><<<g128, 256>>>(ne, hc_w1, hc_b1, hid, Nn, HCH, DOUT);
    hc2_kernel<<<(Nn * NCLS) / 256, 256>>>(hid, hc_w2, hc_b2, hl);
    // global mean
    mean_kernel<<<DOUT, 256>>>(ne, gf);
}

// round 10
// speedup vs baseline: 2.7313x; 1.0326x over previous
#include <cuda_runtime.h>
#include <cuda_bf16.h>

// ---------------- problem constants ----------------
#define Nn      12288
#define Ee      393216
#define Hh      256
#define WPR     384            // Nn/32 words per bitmap row
#define MAXNNZ  (2*Ee)
#define DOUT    128
#define NCLS    8
#define HCH     64             // D_OUT/2

// ---------------- device scratch (static, no allocation) ----------------
__device__ __align__(16) unsigned g_bmA[(size_t)Nn * WPR];   // A[i][j] bit
__device__ __align__(16) unsigned g_bmT[(size_t)Nn * WPR];   // A^T[i][j] bit
__device__ int      g_rowptr[Nn];
__device__ int      g_rowcnt[Nn];
__device__ int      g_col[MAXNNZ];
__device__ float    g_val[MAXNNZ];
__device__ float    g_x0[(size_t)Nn * Hh];
__device__ float    g_x1[(size_t)Nn * Hh];
__device__ float    g_s [(size_t)Nn * Hh];
__device__ float    g_hid[(size_t)Nn * HCH];
__device__ int      g_is64;
__device__ int      g_nnz;

// ---------------- graph build ----------------
__global__ void clear_kernel() {
    int i = blockIdx.x * blockDim.x + threadIdx.x;
    int stride = gridDim.x * blockDim.x;
    const int tot4 = Nn * WPR / 4;
    uint4 z = make_uint4(0u, 0u, 0u, 0u);
    uint4* a = (uint4*)g_bmA;
    uint4* t = (uint4*)g_bmT;
    for (int j = i; j < tot4; j += stride) { a[j] = z; t[j] = z; }
    if (i == 0) g_nnz = 0;
}

// int64-vs-int32 edge_index detection: if data is int64 (values < 12288),
// every odd 32-bit word (hi half) is zero.
__global__ void detect_kernel(const int* __restrict__ ei) {
    __shared__ int sh[256];
    int t = threadIdx.x;
    int v = 0;
    for (int i = t; i < 4096; i += 256) v |= ei[2 * i + 1];
    sh[t] = v; __syncthreads();
    for (int o = 128; o > 0; o >>= 1) { if (t < o) sh[t] |= sh[t + o]; __syncthreads(); }
    if (t == 0) g_is64 = (sh[0] == 0) ? 1 : 0;
}

__global__ void scatter_kernel(const void* __restrict__ ei_raw) {
    int e = blockIdx.x * blockDim.x + threadIdx.x;
    if (e >= Ee) return;
    int s, d;
    if (g_is64) {
        const long long* ei = (const long long*)ei_raw;
        s = (int)ei[e]; d = (int)ei[Ee + e];
    } else {
        const int* ei = (const int*)ei_raw;
        s = ei[e]; d = ei[Ee + e];
    }
    atomicOr(&g_bmA[(size_t)s * WPR + (d >> 5)], 1u << (d & 31));
    atomicOr(&g_bmT[(size_t)d * WPR + (s >> 5)], 1u << (s & 31));
}

// Fused count + allocate + fill: one warp per row, single bitmap pass.
// CSR segment offsets come from a block-aggregated atomicAdd; per-row entry
// content (sorted by column) is invariant, so SpMM output is deterministic.
__global__ void __launch_bounds__(256) fill2_kernel() {
    __shared__ int s_tot[8];
    __shared__ int s_base;
    const int wip  = threadIdx.x >> 5;
    const int lane = threadIdx.x & 31;
    const int row  = blockIdx.x * 8 + wip;

    const uint4* pa = (const uint4*)g_bmA + (size_t)row * (WPR / 4) + lane * 3;
    const uint4* pt = (const uint4*)g_bmT + (size_t)row * (WPR / 4) + lane * 3;
    uint4 A0 = pa[0], A1 = pa[1], A2 = pa[2];
    uint4 T0 = pt[0], T1 = pt[1], T2 = pt[2];
    unsigned aw[12] = {A0.x, A0.y, A0.z, A0.w, A1.x, A1.y, A1.z, A1.w,
                       A2.x, A2.y, A2.z, A2.w};
    unsigned tw[12] = {T0.x, T0.y, T0.z, T0.w, T1.x, T1.y, T1.z, T1.w,
                       T2.x, T2.y, T2.z, T2.w};
    int cu = 0, rs = 0;
#pragma unroll
    for (int i = 0; i < 12; i++) {
        cu += __popc(aw[i] | tw[i]);
        rs += __popc(aw[i]) + __popc(tw[i]);
    }
#pragma unroll
    for (int off = 16; off > 0; off >>= 1)
        rs += __shfl_xor_sync(0xFFFFFFFFu, rs, off);
    int x = cu;                               // inclusive scan of cu over lanes
#pragma unroll
    for (int off = 1; off < 32; off <<= 1) {
        int y = __shfl_up_sync(0xFFFFFFFFu, x, off);
        if (lane >= off) x += y;
    }
    int tot = __shfl_sync(0xFFFFFFFFu, x, 31);

    if (lane == 0) s_tot[wip] = tot;
    __syncthreads();
    if (threadIdx.x == 0) {
        int run = 0;
#pragma unroll
        for (int i = 0; i < 8; i++) { int v = s_tot[i]; s_tot[i] = run; run += v; }
        s_base = atomicAdd(&g_nnz, run);
    }
    __syncthreads();
    int rowbase = s_base + s_tot[wip];

    if (lane == 0) { g_rowptr[row] = rowbase; g_rowcnt[row] = tot; }
    float inv = 1.0f / ((float)rs + 1e-8f);
    int pos = rowbase + x - cu;
#pragma unroll
    for (int i = 0; i < 12; i++) {
        unsigned a = aw[i], t = tw[i], u = a | t;
        int colbase = (lane * 12 + i) * 32;
        while (u) {
            int b = __ffs(u) - 1;
            g_col[pos] = colbase + b;
            g_val[pos] = (float)(((a >> b) & 1u) + ((t >> b) & 1u)) * inv;
            ++pos;
            u &= u - 1;
        }
    }
}

// ---------------- SpMM: s = x + adj_norm @ x   (x: [Nn, 256]) ----------------
__global__ void __launch_bounds__(256) spmm_kernel(const float* __restrict__ x,
                                                   float* __restrict__ s) {
    int row = blockIdx.x;
    int f = threadIdx.x;
    __shared__ int   scol[256];
    __shared__ float sval[256];
    float acc = x[(size_t)row * Hh + f];
    int start = g_rowptr[row];
    int end = start + g_rowcnt[row];
    for (int c = start; c < end; c += 256) {
        int m = end - c; if (m > 256) m = 256;
        if (f < m) { scol[f] = g_col[c + f]; sval[f] = g_val[c + f]; }
        __syncthreads();
#pragma unroll 4
        for (int j = 0; j < m; ++j)
            acc = fmaf(sval[j], x[(size_t)scol[j] * Hh + f], acc);
        __syncthreads();
    }
    s[(size_t)row * Hh + f] = acc;
}

// ---------------- tf32 tensor-core SGEMM:  C = act(A @ W^T + bias) ----------
// A: [M,K] rm, W: [Nout,K] rm, C: [M,Nout]. BM=64, BN=128, BK=16, 256 thr,
// 8 warps (2x4) each computing 32x32 via mma.sync.m16n8k8 tf32, fp32 accum.
// Smem is m-major stride-20: vectorized STS.128 stores, conflict-free LDS.
// Double-buffered, one __syncthreads per K-iter.
__device__ __forceinline__ unsigned f2tf32(float f) {
    unsigned r;
    asm("cvt.rna.tf32.f32 %0, %1;" : "=r"(r) : "f"(f));
    return r;
}

template <int RELU>
__global__ void __launch_bounds__(256, 2)
mma_gemm(const float* __restrict__ A, const float* __restrict__ W,
         const float* __restrict__ bias, float* __restrict__ C,
         int M, int Nout, int K) {
    __shared__ unsigned As[2][64 * 20];    // [m][k] stride 20 (16 + pad 4)
    __shared__ unsigned Ws[2][128 * 20];

    const int tid  = threadIdx.x;
    const int wid  = tid >> 5;
    const int lane = tid & 31;
    const int g    = lane >> 2;        // 0..7
    const int tig  = lane & 3;         // 0..3
    const int wm   = wid & 1;          // 2 warps along M (32 rows each)
    const int wn   = wid >> 1;         // 4 warps along N (32 cols each)
    const int bx = blockIdx.x, by = blockIdx.y;

    const int lr = tid >> 2;           // 0..63
    const int kq = (tid & 3) * 4;      // 0,4,8,12

    float acc[2][4][4];
#pragma unroll
    for (int mt = 0; mt < 2; mt++)
#pragma unroll
        for (int nt = 0; nt < 4; nt++)
#pragma unroll
            for (int i = 0; i < 4; i++) acc[mt][nt][i] = 0.0f;

    const size_t aRow = (size_t)(by * 64 + lr) * K;
    const int wR0 = bx * 128 + lr, wR1 = wR0 + 64;
    const bool v0 = wR0 < Nout, v1 = wR1 < Nout;
    const size_t wRow0 = (size_t)(v0 ? wR0 : 0) * K;
    const size_t wRow1 = (size_t)(v1 ? wR1 : 0) * K;
    const float4 z4 = make_float4(0.f, 0.f, 0.f, 0.f);

    const int kIter = K >> 4;
    float4 a0v = *(const float4*)(A + aRow + kq);
    float4 w0v = v0 ? *(const float4*)(W + wRow0 + kq) : z4;
    float4 w1v = v1 ? *(const float4*)(W + wRow1 + kq) : z4;

    auto stos = [&](int b) {
        uint4 qa = make_uint4(f2tf32(a0v.x), f2tf32(a0v.y), f2tf32(a0v.z), f2tf32(a0v.w));
        uint4 q0 = make_uint4(f2tf32(w0v.x), f2tf32(w0v.y), f2tf32(w0v.z), f2tf32(w0v.w));
        uint4 q1 = make_uint4(f2tf32(w1v.x), f2tf32(w1v.y), f2tf32(w1v.z), f2tf32(w1v.w));
        *(uint4*)&As[b][lr * 20 + kq]        = qa;
        *(uint4*)&Ws[b][lr * 20 + kq]        = q0;
        *(uint4*)&Ws[b][(lr + 64) * 20 + kq] = q1;
    };

    stos(0);
    __syncthreads();

    for (int it = 0; it < kIter; ++it) {
        const int cur = it & 1;
        if (it + 1 < kIter) {
            int off = (it + 1) * 16 + kq;
            a0v = *(const float4*)(A + aRow + off);
            w0v = v0 ? *(const float4*)(W + wRow0 + off) : z4;
            w1v = v1 ? *(const float4*)(W + wRow1 + off) : z4;
        }
#pragma unroll
        for (int ks = 0; ks < 2; ++ks) {
            const int k0 = ks * 8;
            unsigned af[2][4];
#pragma unroll
            for (int mt = 0; mt < 2; mt++) {
                int m = wm * 32 + mt * 16 + g;
                const unsigned* p = &As[cur][m * 20 + k0 + tig];
                af[mt][0] = p[0];
                af[mt][1] = p[160];    // m+8
                af[mt][2] = p[4];      // k+4
                af[mt][3] = p[164];
            }
            unsigned bf[4][2];
#pragma unroll
            for (int nt = 0; nt < 4; nt++) {
                int n = wn * 32 + nt * 8 + g;
                const unsigned* p = &Ws[cur][n * 20 + k0 + tig];
                bf[nt][0] = p[0];
                bf[nt][1] = p[4];
            }
#pragma unroll
            for (int mt = 0; mt < 2; mt++)
#pragma unroll
                for (int nt = 0; nt < 4; nt++) {
                    asm volatile(
                        "mma.sync.aligned.m16n8k8.row.col.f32.tf32.tf32.f32 "
                        "{%0,%1,%2,%3}, {%4,%5,%6,%7}, {%8,%9}, {%0,%1,%2,%3};"
                        : "+f"(acc[mt][nt][0]), "+f"(acc[mt][nt][1]),
                          "+f"(acc[mt][nt][2]), "+f"(acc[mt][nt][3])
                        : "r"(af[mt][0]), "r"(af[mt][1]),
                          "r"(af[mt][2]), "r"(af[mt][3]),
                          "r"(bf[nt][0]), "r"(bf[nt][1]));
                }
        }
        if (it + 1 < kIter) {
            stos((it + 1) & 1);
            __syncthreads();
        }
    }

    // epilogue: bias + optional relu, float2 stores
    const int rBase = by * 64 + wm * 32;
    const int cBase = bx * 128 + wn * 32;
#pragma unroll
    for (int nt = 0; nt < 4; nt++) {
        int c0 = cBase + nt * 8 + 2 * tig;
        if (c0 < Nout) {
            float b0 = bias[c0], b1 = bias[c0 + 1];
#pragma unroll
            for (int mt = 0; mt < 2; mt++) {
                int r0 = rBase + mt * 16 + g;
                float x0 = acc[mt][nt][0] + b0;
                float x1 = acc[mt][nt][1] + b1;
                float x2 = acc[mt][nt][2] + b0;
                float x3 = acc[mt][nt][3] + b1;
                if (RELU) {
                    x0 = fmaxf(x0, 0.f); x1 = fmaxf(x1, 0.f);
                    x2 = fmaxf(x2, 0.f); x3 = fmaxf(x3, 0.f);
                }
                *(float2*)(C + (size_t)r0 * Nout + c0) = make_float2(x0, x1);
                *(float2*)(C + (size_t)(r0 + 8) * Nout + c0) = make_float2(x2, x3);
            }
        }
    }
}

// ---------------- classifier tail:  hl = hid @ hc_w2^T + b2 ----------------
__global__ void __launch_bounds__(256) hc2_kernel(const float* __restrict__ hid,
                                                  const float* __restrict__ w2,
                                                  const float* __restrict__ b2,
                                                  float* __restrict__ out) {
    __shared__ float sw[NCLS * HCH];
    int t = threadIdx.x;
    for (int i = t; i < NCLS * HCH; i += 256) sw[i] = w2[i];
    __syncthreads();
    int g = blockIdx.x * 256 + t;
    int n = g >> 3, c = g & 7;
    float acc = b2[c];
    const float* hrow = hid + (size_t)n * HCH;
    const float* wrow = sw + c * HCH;
#pragma unroll 8
    for (int k = 0; k < HCH; ++k) acc = fmaf(hrow[k], wrow[k], acc);
    out[g] = acc;
}

// ---------------- column mean of node_embeddings ----------------
__global__ void __launch_bounds__(256) mean_kernel(const float* __restrict__ ne,
                                                   float* __restrict__ out) {
    int f = blockIdx.x;        // 0..127
    int t = threadIdx.x;
    float acc = 0.0f;
    for (int r = t; r < Nn; r += 256) acc += ne[(size_t)r * DOUT + f];
    __shared__ float sh[256];
    sh[t] = acc; __syncthreads();
    for (int o = 128; o > 0; o >>= 1) { if (t < o) sh[t] += sh[t + o]; __syncthreads(); }
    if (t == 0) out[f] = sh[0] * (1.0f / (float)Nn);
}

// ---------------- launch ----------------
extern "C" void kernel_launch(void* const* d_in, const int* in_sizes, int n_in,
                              void* d_out, int out_size) {
    const float* X     = (const float*)d_in[0];
    const void*  EI    = d_in[1];
    const float* enc_w1 = (const float*)d_in[2];
    const float* enc_b1 = (const float*)d_in[3];
    const float* enc_w2 = (const float*)d_in[4];
    const float* enc_b2 = (const float*)d_in[5];
    const float* gin_w  = (const float*)d_in[6];
    const float* gin_b  = (const float*)d_in[7];
    const float* gl_w   = (const float*)d_in[8];
    const float* gl_b   = (const float*)d_in[9];
    const float* gout_w = (const float*)d_in[10];
    const float* gout_b = (const float*)d_in[11];
    const float* proj_w = (const float*)d_in[12];
    const float* proj_b = (const float*)d_in[13];
    const float* hc_w1  = (const float*)d_in[14];
    const float* hc_b1  = (const float*)d_in[15];
    const float* hc_w2  = (const float*)d_in[16];
    const float* hc_b2  = (const float*)d_in[17];

    float *x0, *x1, *s, *hid;
    cudaGetSymbolAddress((void**)&x0, g_x0);
    cudaGetSymbolAddress((void**)&x1, g_x1);
    cudaGetSymbolAddress((void**)&s, g_s);
    cudaGetSymbolAddress((void**)&hid, g_hid);

    float* out = (float*)d_out;
    float* ne = out;                       // [Nn, 128]
    float* hl = out + (size_t)Nn * DOUT;   // [Nn, 8]
    float* gf = hl + (size_t)Nn * NCLS;    // [128]

    // graph build (deterministic output, recomputed every call)
    clear_kernel<<<2048, 256>>>();
    detect_kernel<<<1, 256>>>((const int*)EI);
    scatter_kernel<<<Ee / 256, 256>>>(EI);
    fill2_kernel<<<Nn / 8, 256>>>();

    dim3 g256(2, Nn / 64);    // Nout=256
    dim3 g128(1, Nn / 64);    // Nout<=128

    // encoder
    mma_gemm<1><<<g256, 256>>>(X,  enc_w1, enc_b1, x0, Nn, Hh, 256);
    mma_gemm<0><<<g256, 256>>>(x0, enc_w2, enc_b2, x1, Nn, Hh, Hh);
    // GNN input proj
    mma_gemm<1><<<g256, 256>>>(x1, gin_w, gin_b, x0, Nn, Hh, Hh);
    // 3 message-passing layers
    for (int i = 0; i < 3; i++) {
        spmm_kernel<<<Nn, 256>>>(x0, s);
        mma_gemm<1><<<g256, 256>>>(s, gl_w + (size_t)i * Hh * Hh,
                                   gl_b + (size_t)i * Hh, x0, Nn, Hh, Hh);
    }
    // output proj
    mma_gemm<0><<<g256, 256>>>(x0, gout_w, gout_b, x1, Nn, Hh, Hh);
    // node embeddings (written straight to d_out)
    mma_gemm<1><<<g128, 256>>>(x1, proj_w, proj_b, ne, Nn, DOUT, Hh);
    // hierarchy classifier
    mma_gemm<1><<<g128, 256>>>(ne, hc_w1, hc_b1, hid, Nn, HCH, DOUT);
    hc2_kernel<<<(Nn * NCLS) / 256, 256>>>(hid, hc_w2, hc_b2, hl);
    // global mean
    mean_kernel<<<DOUT, 256>>>(ne, gf);
}

// round 11
// speedup vs baseline: 3.4081x; 1.2478x over previous
#include <cuda_runtime.h>
#include <cuda_bf16.h>
#include <cuda_fp16.h>

// ---------------- problem constants ----------------
#define Nn      12288
#define Ee      393216
#define Hh      256
#define WPR     384            // Nn/32 words per bitmap row
#define MAXNNZ  (2*Ee)
#define DOUT    128
#define NCLS    8
#define HCH     64             // D_OUT/2

// ---------------- device scratch (static, no allocation) ----------------
__device__ __align__(16) unsigned g_bmA[(size_t)Nn * WPR];   // A[i][j] bit
__device__ __align__(16) unsigned g_bmT[(size_t)Nn * WPR];   // A^T[i][j] bit
__device__ int      g_rowptr[Nn];
__device__ int      g_rowcnt[Nn];
__device__ int      g_col[MAXNNZ];
__device__ float    g_val[MAXNNZ];
__device__ float    g_x0[(size_t)Nn * Hh];
__device__ float    g_x1[(size_t)Nn * Hh];
__device__ float    g_s [(size_t)Nn * Hh];
__device__ __half   g_xh[(size_t)Nn * Hh];   // fp16 shadow for SpMM gather
__device__ float    g_hid[(size_t)Nn * HCH];
__device__ int      g_is64;
__device__ int      g_nnz;

// ---------------- graph build ----------------
__global__ void clear_kernel() {
    int i = blockIdx.x * blockDim.x + threadIdx.x;
    int stride = gridDim.x * blockDim.x;
    const int tot4 = Nn * WPR / 4;
    uint4 z = make_uint4(0u, 0u, 0u, 0u);
    uint4* a = (uint4*)g_bmA;
    uint4* t = (uint4*)g_bmT;
    for (int j = i; j < tot4; j += stride) { a[j] = z; t[j] = z; }
    if (i == 0) g_nnz = 0;
}

// int64-vs-int32 edge_index detection: if data is int64 (values < 12288),
// every odd 32-bit word (hi half) is zero.
__global__ void detect_kernel(const int* __restrict__ ei) {
    __shared__ int sh[256];
    int t = threadIdx.x;
    int v = 0;
    for (int i = t; i < 4096; i += 256) v |= ei[2 * i + 1];
    sh[t] = v; __syncthreads();
    for (int o = 128; o > 0; o >>= 1) { if (t < o) sh[t] |= sh[t + o]; __syncthreads(); }
    if (t == 0) g_is64 = (sh[0] == 0) ? 1 : 0;
}

__global__ void __launch_bounds__(256) scatter_kernel(const void* __restrict__ ei_raw) {
    int base = blockIdx.x * 1024 + threadIdx.x;
    const int is64 = g_is64;
#pragma unroll
    for (int u = 0; u < 4; u++) {
        int e = base + u * 256;
        int s, d;
        if (is64) {
            const long long* ei = (const long long*)ei_raw;
            s = (int)ei[e]; d = (int)ei[Ee + e];
        } else {
            const int* ei = (const int*)ei_raw;
            s = ei[e]; d = ei[Ee + e];
        }
        atomicOr(&g_bmA[(size_t)s * WPR + (d >> 5)], 1u << (d & 31));
        atomicOr(&g_bmT[(size_t)d * WPR + (s >> 5)], 1u << (s & 31));
    }
}

// Fused count + allocate + fill: one warp per row, single bitmap pass.
// CSR segment offsets come from a block-aggregated atomicAdd; per-row entry
// content (sorted by column) is invariant, so SpMM output is deterministic.
__global__ void __launch_bounds__(256) fill2_kernel() {
    __shared__ int s_tot[8];
    __shared__ int s_base;
    const int wip  = threadIdx.x >> 5;
    const int lane = threadIdx.x & 31;
    const int row  = blockIdx.x * 8 + wip;

    const uint4* pa = (const uint4*)g_bmA + (size_t)row * (WPR / 4) + lane * 3;
    const uint4* pt = (const uint4*)g_bmT + (size_t)row * (WPR / 4) + lane * 3;
    uint4 A0 = pa[0], A1 = pa[1], A2 = pa[2];
    uint4 T0 = pt[0], T1 = pt[1], T2 = pt[2];
    unsigned aw[12] = {A0.x, A0.y, A0.z, A0.w, A1.x, A1.y, A1.z, A1.w,
                       A2.x, A2.y, A2.z, A2.w};
    unsigned tw[12] = {T0.x, T0.y, T0.z, T0.w, T1.x, T1.y, T1.z, T1.w,
                       T2.x, T2.y, T2.z, T2.w};
    int cu = 0, rs = 0;
#pragma unroll
    for (int i = 0; i < 12; i++) {
        cu += __popc(aw[i] | tw[i]);
        rs += __popc(aw[i]) + __popc(tw[i]);
    }
#pragma unroll
    for (int off = 16; off > 0; off >>= 1)
        rs += __shfl_xor_sync(0xFFFFFFFFu, rs, off);
    int x = cu;                               // inclusive scan of cu over lanes
#pragma unroll
    for (int off = 1; off < 32; off <<= 1) {
        int y = __shfl_up_sync(0xFFFFFFFFu, x, off);
        if (lane >= off) x += y;
    }
    int tot = __shfl_sync(0xFFFFFFFFu, x, 31);

    if (lane == 0) s_tot[wip] = tot;
    __syncthreads();
    if (threadIdx.x == 0) {
        int run = 0;
#pragma unroll
        for (int i = 0; i < 8; i++) { int v = s_tot[i]; s_tot[i] = run; run += v; }
        s_base = atomicAdd(&g_nnz, run);
    }
    __syncthreads();
    int rowbase = s_base + s_tot[wip];

    if (lane == 0) { g_rowptr[row] = rowbase; g_rowcnt[row] = tot; }
    float inv = 1.0f / ((float)rs + 1e-8f);
    int pos = rowbase + x - cu;
#pragma unroll
    for (int i = 0; i < 12; i++) {
        unsigned a = aw[i], t = tw[i], u = a | t;
        int colbase = (lane * 12 + i) * 32;
        while (u) {
            int b = __ffs(u) - 1;
            g_col[pos] = colbase + b;
            g_val[pos] = (float)(((a >> b) & 1u) + ((t >> b) & 1u)) * inv;
            ++pos;
            u &= u - 1;
        }
    }
}

// ---------------- SpMM: s = x + adj_norm @ x ------------------------------
// Identity term from fp32 x; gathered neighbor rows from fp16 shadow xh
// (halves L2 gather traffic); fp32 accumulation.
__global__ void __launch_bounds__(128) spmm_kernel(const float* __restrict__ x,
                                                   const __half* __restrict__ xh,
                                                   float* __restrict__ s) {
    int row = blockIdx.x;
    int f2 = threadIdx.x;                     // feature pair 0..127
    __shared__ int   scol[128];
    __shared__ float sval[128];
    float2 acc = ((const float2*)(x + (size_t)row * Hh))[f2];
    int start = g_rowptr[row];
    int end = start + g_rowcnt[row];
    for (int c = start; c < end; c += 128) {
        int m = end - c; if (m > 128) m = 128;
        if (f2 < m) { scol[f2] = g_col[c + f2]; sval[f2] = g_val[c + f2]; }
        __syncthreads();
#pragma unroll 4
        for (int j = 0; j < m; ++j) {
            __half2 h = ((const __half2*)(xh + (size_t)scol[j] * Hh))[f2];
            float2 v = __half22float2(h);
            acc.x = fmaf(sval[j], v.x, acc.x);
            acc.y = fmaf(sval[j], v.y, acc.y);
        }
        __syncthreads();
    }
    ((float2*)(s + (size_t)row * Hh))[f2] = acc;
}

// ---------------- tf32 tensor-core SGEMM:  C = act(A @ W^T + bias) ----------
// A: [M,K] rm, W: [Nout,K] rm, C: [M,Nout]. BM=64, BN=128, BK=16, 256 thr,
// 8 warps (2x4) each computing 32x32 via mma.sync.m16n8k8 tf32, fp32 accum.
// WH: also emit fp16 shadow copy of C for the downstream SpMM gather.
__device__ __forceinline__ unsigned f2tf32(float f) {
    unsigned r;
    asm("cvt.rna.tf32.f32 %0, %1;" : "=r"(r) : "f"(f));
    return r;
}

template <int RELU, int WH>
__global__ void __launch_bounds__(256, 2)
mma_gemm(const float* __restrict__ A, const float* __restrict__ W,
         const float* __restrict__ bias, float* __restrict__ C,
         __half* __restrict__ Ch, int M, int Nout, int K) {
    __shared__ unsigned As[2][64 * 20];    // [m][k] stride 20 (16 + pad 4)
    __shared__ unsigned Ws[2][128 * 20];

    const int tid  = threadIdx.x;
    const int wid  = tid >> 5;
    const int lane = tid & 31;
    const int g    = lane >> 2;        // 0..7
    const int tig  = lane & 3;         // 0..3
    const int wm   = wid & 1;          // 2 warps along M (32 rows each)
    const int wn   = wid >> 1;         // 4 warps along N (32 cols each)
    const int bx = blockIdx.x, by = blockIdx.y;

    const int lr = tid >> 2;           // 0..63
    const int kq = (tid & 3) * 4;      // 0,4,8,12

    float acc[2][4][4];
#pragma unroll
    for (int mt = 0; mt < 2; mt++)
#pragma unroll
        for (int nt = 0; nt < 4; nt++)
#pragma unroll
            for (int i = 0; i < 4; i++) acc[mt][nt][i] = 0.0f;

    const size_t aRow = (size_t)(by * 64 + lr) * K;
    const int wR0 = bx * 128 + lr, wR1 = wR0 + 64;
    const bool v0 = wR0 < Nout, v1 = wR1 < Nout;
    const size_t wRow0 = (size_t)(v0 ? wR0 : 0) * K;
    const size_t wRow1 = (size_t)(v1 ? wR1 : 0) * K;
    const float4 z4 = make_float4(0.f, 0.f, 0.f, 0.f);

    const int kIter = K >> 4;
    float4 a0v = *(const float4*)(A + aRow + kq);
    float4 w0v = v0 ? *(const float4*)(W + wRow0 + kq) : z4;
    float4 w1v = v1 ? *(const float4*)(W + wRow1 + kq) : z4;

    auto stos = [&](int b) {
        uint4 qa = make_uint4(f2tf32(a0v.x), f2tf32(a0v.y), f2tf32(a0v.z), f2tf32(a0v.w));
        uint4 q0 = make_uint4(f2tf32(w0v.x), f2tf32(w0v.y), f2tf32(w0v.z), f2tf32(w0v.w));
        uint4 q1 = make_uint4(f2tf32(w1v.x), f2tf32(w1v.y), f2tf32(w1v.z), f2tf32(w1v.w));
        *(uint4*)&As[b][lr * 20 + kq]        = qa;
        *(uint4*)&Ws[b][lr * 20 + kq]        = q0;
        *(uint4*)&Ws[b][(lr + 64) * 20 + kq] = q1;
    };

    stos(0);
    __syncthreads();

    for (int it = 0; it < kIter; ++it) {
        const int cur = it & 1;
        if (it + 1 < kIter) {
            int off = (it + 1) * 16 + kq;
            a0v = *(const float4*)(A + aRow + off);
            w0v = v0 ? *(const float4*)(W + wRow0 + off) : z4;
            w1v = v1 ? *(const float4*)(W + wRow1 + off) : z4;
        }
#pragma unroll
        for (int ks = 0; ks < 2; ++ks) {
            const int k0 = ks * 8;
            unsigned af[2][4];
#pragma unroll
            for (int mt = 0; mt < 2; mt++) {
                int m = wm * 32 + mt * 16 + g;
                const unsigned* p = &As[cur][m * 20 + k0 + tig];
                af[mt][0] = p[0];
                af[mt][1] = p[160];    // m+8
                af[mt][2] = p[4];      // k+4
                af[mt][3] = p[164];
            }
            unsigned bf[4][2];
#pragma unroll
            for (int nt = 0; nt < 4; nt++) {
                int n = wn * 32 + nt * 8 + g;
                const unsigned* p = &Ws[cur][n * 20 + k0 + tig];
                bf[nt][0] = p[0];
                bf[nt][1] = p[4];
            }
#pragma unroll
            for (int mt = 0; mt < 2; mt++)
#pragma unroll
                for (int nt = 0; nt < 4; nt++) {
                    asm volatile(
                        "mma.sync.aligned.m16n8k8.row.col.f32.tf32.tf32.f32 "
                        "{%0,%1,%2,%3}, {%4,%5,%6,%7}, {%8,%9}, {%0,%1,%2,%3};"
                        : "+f"(acc[mt][nt][0]), "+f"(acc[mt][nt][1]),
                          "+f"(acc[mt][nt][2]), "+f"(acc[mt][nt][3])
                        : "r"(af[mt][0]), "r"(af[mt][1]),
                          "r"(af[mt][2]), "r"(af[mt][3]),
                          "r"(bf[nt][0]), "r"(bf[nt][1]));
                }
        }
        if (it + 1 < kIter) {
            stos((it + 1) & 1);
            __syncthreads();
        }
    }

    // epilogue: bias + optional relu (+ fp16 shadow), float2 stores
    const int rBase = by * 64 + wm * 32;
    const int cBase = bx * 128 + wn * 32;
#pragma unroll
    for (int nt = 0; nt < 4; nt++) {
        int c0 = cBase + nt * 8 + 2 * tig;
        if (c0 < Nout) {
            float b0 = bias[c0], b1 = bias[c0 + 1];
#pragma unroll
            for (int mt = 0; mt < 2; mt++) {
                int r0 = rBase + mt * 16 + g;
                float x0 = acc[mt][nt][0] + b0;
                float x1 = acc[mt][nt][1] + b1;
                float x2 = acc[mt][nt][2] + b0;
                float x3 = acc[mt][nt][3] + b1;
                if (RELU) {
                    x0 = fmaxf(x0, 0.f); x1 = fmaxf(x1, 0.f);
                    x2 = fmaxf(x2, 0.f); x3 = fmaxf(x3, 0.f);
                }
                *(float2*)(C + (size_t)r0 * Nout + c0) = make_float2(x0, x1);
                *(float2*)(C + (size_t)(r0 + 8) * Nout + c0) = make_float2(x2, x3);
                if (WH) {
                    *(__half2*)(Ch + (size_t)r0 * Nout + c0) =
                        __float22half2_rn(make_float2(x0, x1));
                    *(__half2*)(Ch + (size_t)(r0 + 8) * Nout + c0) =
                        __float22half2_rn(make_float2(x2, x3));
                }
            }
        }
    }
}

// ---------------- classifier tail:  hl = hid @ hc_w2^T + b2 ----------------
__global__ void __launch_bounds__(256) hc2_kernel(const float* __restrict__ hid,
                                                  const float* __restrict__ w2,
                                                  const float* __restrict__ b2,
                                                  float* __restrict__ out) {
    __shared__ float sw[NCLS * HCH];
    int t = threadIdx.x;
    for (int i = t; i < NCLS * HCH; i += 256) sw[i] = w2[i];
    __syncthreads();
    int g = blockIdx.x * 256 + t;
    int n = g >> 3, c = g & 7;
    float acc = b2[c];
    const float* hrow = hid + (size_t)n * HCH;
    const float* wrow = sw + c * HCH;
#pragma unroll 8
    for (int k = 0; k < HCH; ++k) acc = fmaf(hrow[k], wrow[k], acc);
    out[g] = acc;
}

// ---------------- column mean of node_embeddings ----------------
__global__ void __launch_bounds__(256) mean_kernel(const float* __restrict__ ne,
                                                   float* __restrict__ out) {
    int f = blockIdx.x;        // 0..127
    int t = threadIdx.x;
    float acc = 0.0f;
    for (int r = t; r < Nn; r += 256) acc += ne[(size_t)r * DOUT + f];
    __shared__ float sh[256];
    sh[t] = acc; __syncthreads();
    for (int o = 128; o > 0; o >>= 1) { if (t < o) sh[t] += sh[t + o]; __syncthreads(); }
    if (t == 0) out[f] = sh[0] * (1.0f / (float)Nn);
}

// ---------------- streams/events (created once at static init) -------------
struct AuxRes {
    cudaStream_t s = nullptr;
    cudaEvent_t fork1 = nullptr, join1 = nullptr, fork2 = nullptr, join2 = nullptr;
    bool ok = false;
    AuxRes() {
        ok = (cudaStreamCreateWithFlags(&s, cudaStreamNonBlocking) == cudaSuccess)
          && (cudaEventCreateWithFlags(&fork1, cudaEventDisableTiming) == cudaSuccess)
          && (cudaEventCreateWithFlags(&join1, cudaEventDisableTiming) == cudaSuccess)
          && (cudaEventCreateWithFlags(&fork2, cudaEventDisableTiming) == cudaSuccess)
          && (cudaEventCreateWithFlags(&join2, cudaEventDisableTiming) == cudaSuccess);
    }
};
static AuxRes g_aux;

// ---------------- launch ----------------
extern "C" void kernel_launch(void* const* d_in, const int* in_sizes, int n_in,
                              void* d_out, int out_size) {
    const float* X     = (const float*)d_in[0];
    const void*  EI    = d_in[1];
    const float* enc_w1 = (const float*)d_in[2];
    const float* enc_b1 = (const float*)d_in[3];
    const float* enc_w2 = (const float*)d_in[4];
    const float* enc_b2 = (const float*)d_in[5];
    const float* gin_w  = (const float*)d_in[6];
    const float* gin_b  = (const float*)d_in[7];
    const float* gl_w   = (const float*)d_in[8];
    const float* gl_b   = (const float*)d_in[9];
    const float* gout_w = (const float*)d_in[10];
    const float* gout_b = (const float*)d_in[11];
    const float* proj_w = (const float*)d_in[12];
    const float* proj_b = (const float*)d_in[13];
    const float* hc_w1  = (const float*)d_in[14];
    const float* hc_b1  = (const float*)d_in[15];
    const float* hc_w2  = (const float*)d_in[16];
    const float* hc_b2  = (const float*)d_in[17];

    float *x0, *x1, *s, *hid;
    __half* xh;
    cudaGetSymbolAddress((void**)&x0, g_x0);
    cudaGetSymbolAddress((void**)&x1, g_x1);
    cudaGetSymbolAddress((void**)&s, g_s);
    cudaGetSymbolAddress((void**)&xh, g_xh);
    cudaGetSymbolAddress((void**)&hid, g_hid);

    float* out = (float*)d_out;
    float* ne = out;                       // [Nn, 128]
    float* hl = out + (size_t)Nn * DOUT;   // [Nn, 8]
    float* gf = hl + (size_t)Nn * NCLS;    // [128]

    const bool fork = g_aux.ok;
    cudaStream_t sb = fork ? g_aux.s : (cudaStream_t)0;   // build stream

    // --- graph build (aux stream when available, overlapped with encoder) ---
    if (fork) {
        cudaEventRecord(g_aux.fork1, 0);
        cudaStreamWaitEvent(sb, g_aux.fork1, 0);
    }
    clear_kernel<<<2048, 256, 0, sb>>>();
    detect_kernel<<<1, 256, 0, sb>>>((const int*)EI);
    scatter_kernel<<<Ee / 1024, 256, 0, sb>>>(EI);
    fill2_kernel<<<Nn / 8, 256, 0, sb>>>();
    if (fork) cudaEventRecord(g_aux.join1, sb);

    dim3 g256(2, Nn / 64);    // Nout=256
    dim3 g128(1, Nn / 64);    // Nout<=128

    // --- encoder (default stream, overlaps graph build) ---
    mma_gemm<1, 0><<<g256, 256>>>(X,  enc_w1, enc_b1, x0, nullptr, Nn, Hh, 256);
    mma_gemm<0, 0><<<g256, 256>>>(x0, enc_w2, enc_b2, x1, nullptr, Nn, Hh, Hh);
    mma_gemm<1, 1><<<g256, 256>>>(x1, gin_w, gin_b, x0, xh, Nn, Hh, Hh);

    if (fork) cudaStreamWaitEvent(0, g_aux.join1, 0);  // join: CSR ready

    // --- 3 message-passing layers ---
    for (int i = 0; i < 3; i++) {
        spmm_kernel<<<Nn, 128>>>(x0, xh, s);
        if (i < 2)
            mma_gemm<1, 1><<<g256, 256>>>(s, gl_w + (size_t)i * Hh * Hh,
                                          gl_b + (size_t)i * Hh, x0, xh, Nn, Hh, Hh);
        else
            mma_gemm<1, 0><<<g256, 256>>>(s, gl_w + (size_t)i * Hh * Hh,
                                          gl_b + (size_t)i * Hh, x0, nullptr, Nn, Hh, Hh);
    }
    // output proj
    mma_gemm<0, 0><<<g256, 256>>>(x0, gout_w, gout_b, x1, nullptr, Nn, Hh, Hh);
    // node embeddings (written straight to d_out)
    mma_gemm<1, 0><<<g128, 256>>>(x1, proj_w, proj_b, ne, nullptr, Nn, DOUT, Hh);

    // --- tail: mean on aux stream concurrent with classifier ---
    if (fork) {
        cudaEventRecord(g_aux.fork2, 0);
        cudaStreamWaitEvent(sb, g_aux.fork2, 0);
    }
    mean_kernel<<<DOUT, 256, 0, sb>>>(ne, gf);
    if (fork) cudaEventRecord(g_aux.join2, sb);

    mma_gemm<1, 0><<<g128, 256>>>(ne, hc_w1, hc_b1, hid, nullptr, Nn, HCH, DOUT);
    hc2_kernel<<<(Nn * NCLS) / 256, 256>>>(hid, hc_w2, hc_b2, hl);

    if (fork) cudaStreamWaitEvent(0, g_aux.join2, 0);
}

// round 12
// speedup vs baseline: 4.0256x; 1.1812x over previous
#include <cuda_runtime.h>
#include <cuda_bf16.h>
#include <cuda_fp16.h>

// ---------------- problem constants ----------------
#define Nn      12288
#define Ee      393216
#define Hh      256
#define WPR     384            // Nn/32 words per bitmap row
#define MAXNNZ  (2*Ee)
#define DOUT    128
#define NCLS    8
#define HCH     64             // D_OUT/2

// ---------------- device scratch (static, no allocation) ----------------
__device__ __align__(16) unsigned g_bmA[(size_t)Nn * WPR];   // A[i][j] bit
__device__ __align__(16) unsigned g_bmT[(size_t)Nn * WPR];   // A^T[i][j] bit
__device__ int      g_rowptr[Nn];
__device__ int      g_rowcnt[Nn];
__device__ int      g_col[MAXNNZ];
__device__ float    g_val[MAXNNZ];
__device__ __align__(16) __half g_ha[(size_t)Nn * Hh];   // activation ping
__device__ __align__(16) __half g_hb[(size_t)Nn * Hh];   // activation pong
__device__ __align__(16) __half g_neh[(size_t)Nn * DOUT];
__device__ float    g_hid[(size_t)Nn * HCH];
__device__ int      g_is64;
__device__ int      g_nnz;

// ---------------- graph build ----------------
__global__ void clear_kernel() {
    int i = blockIdx.x * blockDim.x + threadIdx.x;
    int stride = gridDim.x * blockDim.x;
    const int tot4 = Nn * WPR / 4;
    uint4 z = make_uint4(0u, 0u, 0u, 0u);
    uint4* a = (uint4*)g_bmA;
    uint4* t = (uint4*)g_bmT;
    for (int j = i; j < tot4; j += stride) { a[j] = z; t[j] = z; }
    if (i == 0) g_nnz = 0;
}

// int64-vs-int32 edge_index detection: if data is int64 (values < 12288),
// every odd 32-bit word (hi half) is zero.
__global__ void detect_kernel(const int* __restrict__ ei) {
    __shared__ int sh[256];
    int t = threadIdx.x;
    int v = 0;
    for (int i = t; i < 4096; i += 256) v |= ei[2 * i + 1];
    sh[t] = v; __syncthreads();
    for (int o = 128; o > 0; o >>= 1) { if (t < o) sh[t] |= sh[t + o]; __syncthreads(); }
    if (t == 0) g_is64 = (sh[0] == 0) ? 1 : 0;
}

__global__ void __launch_bounds__(256) scatter_kernel(const void* __restrict__ ei_raw) {
    int base = blockIdx.x * 1024 + threadIdx.x;
    const int is64 = g_is64;
#pragma unroll
    for (int u = 0; u < 4; u++) {
        int e = base + u * 256;
        int s, d;
        if (is64) {
            const long long* ei = (const long long*)ei_raw;
            s = (int)ei[e]; d = (int)ei[Ee + e];
        } else {
            const int* ei = (const int*)ei_raw;
            s = ei[e]; d = ei[Ee + e];
        }
        atomicOr(&g_bmA[(size_t)s * WPR + (d >> 5)], 1u << (d & 31));
        atomicOr(&g_bmT[(size_t)d * WPR + (s >> 5)], 1u << (s & 31));
    }
}

// Fused count + allocate + fill: one warp per row, single bitmap pass.
// CSR segment offsets come from a block-aggregated atomicAdd; per-row entry
// content (sorted by column) is invariant, so SpMM output is deterministic.
__global__ void __launch_bounds__(256) fill2_kernel() {
    __shared__ int s_tot[8];
    __shared__ int s_base;
    const int wip  = threadIdx.x >> 5;
    const int lane = threadIdx.x & 31;
    const int row  = blockIdx.x * 8 + wip;

    const uint4* pa = (const uint4*)g_bmA + (size_t)row * (WPR / 4) + lane * 3;
    const uint4* pt = (const uint4*)g_bmT + (size_t)row * (WPR / 4) + lane * 3;
    uint4 A0 = pa[0], A1 = pa[1], A2 = pa[2];
    uint4 T0 = pt[0], T1 = pt[1], T2 = pt[2];
    unsigned aw[12] = {A0.x, A0.y, A0.z, A0.w, A1.x, A1.y, A1.z, A1.w,
                       A2.x, A2.y, A2.z, A2.w};
    unsigned tw[12] = {T0.x, T0.y, T0.z, T0.w, T1.x, T1.y, T1.z, T1.w,
                       T2.x, T2.y, T2.z, T2.w};
    int cu = 0, rs = 0;
#pragma unroll
    for (int i = 0; i < 12; i++) {
        cu += __popc(aw[i] | tw[i]);
        rs += __popc(aw[i]) + __popc(tw[i]);
    }
#pragma unroll
    for (int off = 16; off > 0; off >>= 1)
        rs += __shfl_xor_sync(0xFFFFFFFFu, rs, off);
    int x = cu;                               // inclusive scan of cu over lanes
#pragma unroll
    for (int off = 1; off < 32; off <<= 1) {
        int y = __shfl_up_sync(0xFFFFFFFFu, x, off);
        if (lane >= off) x += y;
    }
    int tot = __shfl_sync(0xFFFFFFFFu, x, 31);

    if (lane == 0) s_tot[wip] = tot;
    __syncthreads();
    if (threadIdx.x == 0) {
        int run = 0;
#pragma unroll
        for (int i = 0; i < 8; i++) { int v = s_tot[i]; s_tot[i] = run; run += v; }
        s_base = atomicAdd(&g_nnz, run);
    }
    __syncthreads();
    int rowbase = s_base + s_tot[wip];

    if (lane == 0) { g_rowptr[row] = rowbase; g_rowcnt[row] = tot; }
    float inv = 1.0f / ((float)rs + 1e-8f);
    int pos = rowbase + x - cu;
#pragma unroll
    for (int i = 0; i < 12; i++) {
        unsigned a = aw[i], t = tw[i], u = a | t;
        int colbase = (lane * 12 + i) * 32;
        while (u) {
            int b = __ffs(u) - 1;
            g_col[pos] = colbase + b;
            g_val[pos] = (float)(((a >> b) & 1u) + ((t >> b) & 1u)) * inv;
            ++pos;
            u &= u - 1;
        }
    }
}

// ---------------- SpMM: s = x + adj_norm @ x  (fp16 in/out, fp32 accum) -----
__global__ void __launch_bounds__(128) spmm_kernel(const __half* __restrict__ xh,
                                                   __half* __restrict__ sh) {
    int row = blockIdx.x;
    int f2 = threadIdx.x;                     // feature pair 0..127
    __shared__ int   scol[128];
    __shared__ float sval[128];
    float2 acc = __half22float2(((const __half2*)(xh + (size_t)row * Hh))[f2]);
    int start = g_rowptr[row];
    int end = start + g_rowcnt[row];
    for (int c = start; c < end; c += 128) {
        int m = end - c; if (m > 128) m = 128;
        if (f2 < m) { scol[f2] = g_col[c + f2]; sval[f2] = g_val[c + f2]; }
        __syncthreads();
#pragma unroll 4
        for (int j = 0; j < m; ++j) {
            __half2 h = ((const __half2*)(xh + (size_t)scol[j] * Hh))[f2];
            float2 v = __half22float2(h);
            acc.x = fmaf(sval[j], v.x, acc.x);
            acc.y = fmaf(sval[j], v.y, acc.y);
        }
        __syncthreads();
    }
    ((__half2*)(sh + (size_t)row * Hh))[f2] = __floats2half2_rn(acc.x, acc.y);
}

// ---------------- fp16 tensor-core GEMM:  C = act(A @ W^T + bias) ----------
// A: [M,K] (fp16, or fp32 when AF32), W: [Nout,K] fp32, fp32 accumulate.
// BM=64, BN=128, BK=32, 256 thr, 8 warps (2x4), mma.m16n8k16.f16.
// Smem: one 32-bit word = half2 k-pair; stride-20-word rows -> conflict-free.
// WF: write fp32 C;  WH: write fp16 Ch.
__device__ __forceinline__ unsigned packh2(float a, float b) {
    __half2 h = __floats2half2_rn(a, b);
    return *(unsigned*)&h;
}

template <int RELU, int WF, int WH, int AF32>
__global__ void __launch_bounds__(256, 2)
hmma_gemm(const void* __restrict__ Ain, const float* __restrict__ W,
          const float* __restrict__ bias, float* __restrict__ C,
          __half* __restrict__ Ch, int M, int Nout, int K) {
    __shared__ unsigned As[2][64 * 20];    // [m][kp] stride 20 (16 + pad 4)
    __shared__ unsigned Ws[2][128 * 20];

    const int tid  = threadIdx.x;
    const int wid  = tid >> 5;
    const int lane = tid & 31;
    const int g    = lane >> 2;        // 0..7
    const int tig  = lane & 3;         // 0..3
    const int wm   = wid & 1;          // 2 warps along M (32 rows each)
    const int wn   = wid >> 1;         // 4 warps along N (32 cols each)
    const int bx = blockIdx.x, by = blockIdx.y;

    const int lr  = tid >> 2;          // 0..63
    const int kq  = (tid & 3) * 4;     // word offset 0,4,8,12
    const int kq8 = (tid & 3) * 8;     // element offset 0,8,16,24

    const __half* Ah = (const __half*)Ain;
    const float*  Af = (const float*)Ain;

    float acc[2][4][4];
#pragma unroll
    for (int mt = 0; mt < 2; mt++)
#pragma unroll
        for (int nt = 0; nt < 4; nt++)
#pragma unroll
            for (int i = 0; i < 4; i++) acc[mt][nt][i] = 0.0f;

    const size_t aRow = (size_t)(by * 64 + lr) * K;
    const int wR0 = bx * 128 + lr, wR1 = wR0 + 64;
    const bool v0 = wR0 < Nout, v1 = wR1 < Nout;
    const size_t wRow0 = (size_t)(v0 ? wR0 : 0) * K;
    const size_t wRow1 = (size_t)(v1 ? wR1 : 0) * K;
    const float4 z4 = make_float4(0.f, 0.f, 0.f, 0.f);

    const int kIter = K >> 5;
    uint4 qa, qw0, qw1;

    auto loadg = [&](int it) {
        const int koff = it * 32 + kq8;
        if (AF32) {
            float4 f0 = *(const float4*)(Af + aRow + koff);
            float4 f1 = *(const float4*)(Af + aRow + koff + 4);
            qa = make_uint4(packh2(f0.x, f0.y), packh2(f0.z, f0.w),
                            packh2(f1.x, f1.y), packh2(f1.z, f1.w));
        } else {
            qa = *(const uint4*)(Ah + aRow + koff);
        }
        float4 f0 = v0 ? *(const float4*)(W + wRow0 + koff) : z4;
        float4 f1 = v0 ? *(const float4*)(W + wRow0 + koff + 4) : z4;
        qw0 = make_uint4(packh2(f0.x, f0.y), packh2(f0.z, f0.w),
                         packh2(f1.x, f1.y), packh2(f1.z, f1.w));
        f0 = v1 ? *(const float4*)(W + wRow1 + koff) : z4;
        f1 = v1 ? *(const float4*)(W + wRow1 + koff + 4) : z4;
        qw1 = make_uint4(packh2(f0.x, f0.y), packh2(f0.z, f0.w),
                         packh2(f1.x, f1.y), packh2(f1.z, f1.w));
    };
    auto stos = [&](int b) {
        *(uint4*)&As[b][lr * 20 + kq]        = qa;
        *(uint4*)&Ws[b][lr * 20 + kq]        = qw0;
        *(uint4*)&Ws[b][(lr + 64) * 20 + kq] = qw1;
    };

    loadg(0);
    stos(0);
    __syncthreads();

    for (int it = 0; it < kIter; ++it) {
        const int cur = it & 1;
        if (it + 1 < kIter) loadg(it + 1);
#pragma unroll
        for (int ks = 0; ks < 2; ++ks) {        // two k16 steps per BK=32
            const int kp0 = ks * 8;
            unsigned af[2][4];
#pragma unroll
            for (int mt = 0; mt < 2; mt++) {
                int m = wm * 32 + mt * 16 + g;
                const unsigned* p = &As[cur][m * 20 + kp0 + tig];
                af[mt][0] = p[0];       // row m,   k 2tig..2tig+1
                af[mt][1] = p[160];     // row m+8
                af[mt][2] = p[4];       // row m,   k 2tig+8..
                af[mt][3] = p[164];
            }
            unsigned bf[4][2];
#pragma unroll
            for (int nt = 0; nt < 4; nt++) {
                int n = wn * 32 + nt * 8 + g;
                const unsigned* p = &Ws[cur][n * 20 + kp0 + tig];
                bf[nt][0] = p[0];
                bf[nt][1] = p[4];
            }
#pragma unroll
            for (int mt = 0; mt < 2; mt++)
#pragma unroll
                for (int nt = 0; nt < 4; nt++) {
                    asm volatile(
                        "mma.sync.aligned.m16n8k16.row.col.f32.f16.f16.f32 "
                        "{%0,%1,%2,%3}, {%4,%5,%6,%7}, {%8,%9}, {%0,%1,%2,%3};"
                        : "+f"(acc[mt][nt][0]), "+f"(acc[mt][nt][1]),
                          "+f"(acc[mt][nt][2]), "+f"(acc[mt][nt][3])
                        : "r"(af[mt][0]), "r"(af[mt][1]),
                          "r"(af[mt][2]), "r"(af[mt][3]),
                          "r"(bf[nt][0]), "r"(bf[nt][1]));
                }
        }
        if (it + 1 < kIter) {
            stos((it + 1) & 1);
            __syncthreads();
        }
    }

    // epilogue: bias + optional relu; fp32 and/or fp16 stores
    const int rBase = by * 64 + wm * 32;
    const int cBase = bx * 128 + wn * 32;
#pragma unroll
    for (int nt = 0; nt < 4; nt++) {
        int c0 = cBase + nt * 8 + 2 * tig;
        if (c0 < Nout) {
            float b0 = bias[c0], b1 = bias[c0 + 1];
#pragma unroll
            for (int mt = 0; mt < 2; mt++) {
                int r0 = rBase + mt * 16 + g;
                float x0 = acc[mt][nt][0] + b0;
                float x1 = acc[mt][nt][1] + b1;
                float x2 = acc[mt][nt][2] + b0;
                float x3 = acc[mt][nt][3] + b1;
                if (RELU) {
                    x0 = fmaxf(x0, 0.f); x1 = fmaxf(x1, 0.f);
                    x2 = fmaxf(x2, 0.f); x3 = fmaxf(x3, 0.f);
                }
                if (WF) {
                    *(float2*)(C + (size_t)r0 * Nout + c0) = make_float2(x0, x1);
                    *(float2*)(C + (size_t)(r0 + 8) * Nout + c0) = make_float2(x2, x3);
                }
                if (WH) {
                    *(unsigned*)(Ch + (size_t)r0 * Nout + c0) = packh2(x0, x1);
                    *(unsigned*)(Ch + (size_t)(r0 + 8) * Nout + c0) = packh2(x2, x3);
                }
            }
        }
    }
}

// ---------------- classifier tail:  hl = hid @ hc_w2^T + b2 ----------------
__global__ void __launch_bounds__(256) hc2_kernel(const float* __restrict__ hid,
                                                  const float* __restrict__ w2,
                                                  const float* __restrict__ b2,
                                                  float* __restrict__ out) {
    __shared__ float sw[NCLS * HCH];
    int t = threadIdx.x;
    for (int i = t; i < NCLS * HCH; i += 256) sw[i] = w2[i];
    __syncthreads();
    int g = blockIdx.x * 256 + t;
    int n = g >> 3, c = g & 7;
    float acc = b2[c];
    const float* hrow = hid + (size_t)n * HCH;
    const float* wrow = sw + c * HCH;
#pragma unroll 8
    for (int k = 0; k < HCH; ++k) acc = fmaf(hrow[k], wrow[k], acc);
    out[g] = acc;
}

// ---------------- column mean of node_embeddings ----------------
__global__ void __launch_bounds__(256) mean_kernel(const float* __restrict__ ne,
                                                   float* __restrict__ out) {
    int f = blockIdx.x;        // 0..127
    int t = threadIdx.x;
    float acc = 0.0f;
    for (int r = t; r < Nn; r += 256) acc += ne[(size_t)r * DOUT + f];
    __shared__ float sh[256];
    sh[t] = acc; __syncthreads();
    for (int o = 128; o > 0; o >>= 1) { if (t < o) sh[t] += sh[t + o]; __syncthreads(); }
    if (t == 0) out[f] = sh[0] * (1.0f / (float)Nn);
}

// ---------------- streams/events (created once at static init) -------------
struct AuxRes {
    cudaStream_t s = nullptr;
    cudaEvent_t fork1 = nullptr, join1 = nullptr, fork2 = nullptr, join2 = nullptr;
    bool ok = false;
    AuxRes() {
        ok = (cudaStreamCreateWithFlags(&s, cudaStreamNonBlocking) == cudaSuccess)
          && (cudaEventCreateWithFlags(&fork1, cudaEventDisableTiming) == cudaSuccess)
          && (cudaEventCreateWithFlags(&join1, cudaEventDisableTiming) == cudaSuccess)
          && (cudaEventCreateWithFlags(&fork2, cudaEventDisableTiming) == cudaSuccess)
          && (cudaEventCreateWithFlags(&join2, cudaEventDisableTiming) == cudaSuccess);
    }
};
static AuxRes g_aux;

// ---------------- launch ----------------
extern "C" void kernel_launch(void* const* d_in, const int* in_sizes, int n_in,
                              void* d_out, int out_size) {
    const float* X     = (const float*)d_in[0];
    const void*  EI    = d_in[1];
    const float* enc_w1 = (const float*)d_in[2];
    const float* enc_b1 = (const float*)d_in[3];
    const float* enc_w2 = (const float*)d_in[4];
    const float* enc_b2 = (const float*)d_in[5];
    const float* gin_w  = (const float*)d_in[6];
    const float* gin_b  = (const float*)d_in[7];
    const float* gl_w   = (const float*)d_in[8];
    const float* gl_b   = (const float*)d_in[9];
    const float* gout_w = (const float*)d_in[10];
    const float* gout_b = (const float*)d_in[11];
    const float* proj_w = (const float*)d_in[12];
    const float* proj_b = (const float*)d_in[13];
    const float* hc_w1  = (const float*)d_in[14];
    const float* hc_b1  = (const float*)d_in[15];
    const float* hc_w2  = (const float*)d_in[16];
    const float* hc_b2  = (const float*)d_in[17];

    __half *hA, *hB, *neh;
    float *hid;
    cudaGetSymbolAddress((void**)&hA, g_ha);
    cudaGetSymbolAddress((void**)&hB, g_hb);
    cudaGetSymbolAddress((void**)&neh, g_neh);
    cudaGetSymbolAddress((void**)&hid, g_hid);

    float* out = (float*)d_out;
    float* ne = out;                       // [Nn, 128]
    float* hl = out + (size_t)Nn * DOUT;   // [Nn, 8]
    float* gf = hl + (size_t)Nn * NCLS;    // [128]

    const bool fork = g_aux.ok;
    cudaStream_t sb = fork ? g_aux.s : (cudaStream_t)0;   // build stream

    // --- graph build (aux stream, overlapped with encoder) ---
    if (fork) {
        cudaEventRecord(g_aux.fork1, 0);
        cudaStreamWaitEvent(sb, g_aux.fork1, 0);
    }
    clear_kernel<<<2048, 256, 0, sb>>>();
    detect_kernel<<<1, 256, 0, sb>>>((const int*)EI);
    scatter_kernel<<<Ee / 1024, 256, 0, sb>>>(EI);
    fill2_kernel<<<Nn / 8, 256, 0, sb>>>();
    if (fork) cudaEventRecord(g_aux.join1, sb);

    dim3 g256(2, Nn / 64);    // Nout=256
    dim3 g128(1, Nn / 64);    // Nout<=128

    // --- encoder (default stream, overlaps graph build) ---
    hmma_gemm<1,0,1,1><<<g256, 256>>>(X,  enc_w1, enc_b1, nullptr, hA, Nn, Hh, 256);
    hmma_gemm<0,0,1,0><<<g256, 256>>>(hA, enc_w2, enc_b2, nullptr, hB, Nn, Hh, Hh);
    hmma_gemm<1,0,1,0><<<g256, 256>>>(hB, gin_w,  gin_b,  nullptr, hA, Nn, Hh, Hh);

    if (fork) cudaStreamWaitEvent(0, g_aux.join1, 0);  // join: CSR ready

    // --- 3 message-passing layers (all-fp16 activations, fp32 accum) ---
    for (int i = 0; i < 3; i++) {
        spmm_kernel<<<Nn, 128>>>(hA, hB);
        hmma_gemm<1,0,1,0><<<g256, 256>>>(hB, gl_w + (size_t)i * Hh * Hh,
                                          gl_b + (size_t)i * Hh, nullptr, hA,
                                          Nn, Hh, Hh);
    }
    // output proj
    hmma_gemm<0,0,1,0><<<g256, 256>>>(hA, gout_w, gout_b, nullptr, hB, Nn, Hh, Hh);
    // node embeddings: fp32 to d_out + fp16 shadow for classifier
    hmma_gemm<1,1,1,0><<<g128, 256>>>(hB, proj_w, proj_b, ne, neh, Nn, DOUT, Hh);

    // --- tail: mean on aux stream concurrent with classifier ---
    if (fork) {
        cudaEventRecord(g_aux.fork2, 0);
        cudaStreamWaitEvent(sb, g_aux.fork2, 0);
    }
    mean_kernel<<<DOUT, 256, 0, sb>>>(ne, gf);
    if (fork) cudaEventRecord(g_aux.join2, sb);

    hmma_gemm<1,1,0,0><<<g128, 256>>>(neh, hc_w1, hc_b1, hid, nullptr, Nn, HCH, DOUT);
    hc2_kernel<<<(Nn * NCLS) / 256, 256>>>(hid, hc_w2, hc_b2, hl);

    if (fork) cudaStreamWaitEvent(0, g_aux.join2, 0);
}